// round 12
// baseline (speedup 1.0000x reference)
#include <cuda_runtime.h>

// SparseGCNLayer: out = relu( segment_sum( (X@W)[src] * val -> dst ) )
// N = 100000, E = 1600000, 64 -> 64 features, fp32.
//
// R10: fused gemm+place (validated in R9) + R8-style agg (validated) with
// the main loop widened 4 -> 8 edges in flight. No predicated gathers, no
// half-warp address splitting (R9's regression).

#define NN  100000
#define NE  1600000
#define CAP 80            // max degree capacity; Poisson(16) tail << 1e-30

// -------- scratch (__device__ globals; zero-initialized .bss) ---------
__device__ __align__(16) static float              g_h[NN * 64];             // X @ W
__device__ __align__(16) static int                g_count[NN];              // per-dst degree (reset by agg)
__device__ __align__(16) static unsigned long long g_edge[(size_t)NN * CAP]; // hi: val bits, lo: src

// ---------------------------------------------------------------------
// K1 (fat): blocks [0, gemm_blocks) do h = X @ W (64x64 tile, 4x4/thread);
//           blocks [gemm_blocks, ...) scatter edges into dst buckets.
// ---------------------------------------------------------------------
__global__ void fused_gemm_place_kernel(const float4* __restrict__ X4,
                                        const float4* __restrict__ W4,
                                        const int*    __restrict__ src,
                                        const int*    __restrict__ dst,
                                        const float*  __restrict__ val,
                                        int n_nodes, int n_edges,
                                        int gemm_blocks) {
    __shared__ float Ws[64][64];
    __shared__ float Xs[64][68];      // padded to dodge bank conflicts

    const int tid = threadIdx.x;      // 256 threads

    if (blockIdx.x < gemm_blocks) {
        // ---------------- GEMM role ----------------
        const int row0 = blockIdx.x * 64;

        for (int k = tid; k < 1024; k += 256) {
            float4 w = W4[k];
            int j = k >> 4, c = (k & 15) * 4;
            Ws[j][c + 0] = w.x; Ws[j][c + 1] = w.y;
            Ws[j][c + 2] = w.z; Ws[j][c + 3] = w.w;
        }
        for (int k = tid; k < 1024; k += 256) {
            int r = k >> 4, cq = (k & 15);
            int row = row0 + r;
            float4 x = (row < n_nodes) ? X4[row * 16 + cq]
                                       : make_float4(0.f, 0.f, 0.f, 0.f);
            int c = cq * 4;
            Xs[r][c + 0] = x.x; Xs[r][c + 1] = x.y;
            Xs[r][c + 2] = x.z; Xs[r][c + 3] = x.w;
        }
        __syncthreads();

        const int cg = tid & 15;
        const int rg = tid >> 4;
        const int c0 = cg * 4;
        const int r0 = rg * 4;

        float acc[4][4] = {};
#pragma unroll
        for (int j = 0; j < 64; j++) {
            float4 w = *(const float4*)&Ws[j][c0];
            float x0 = Xs[r0 + 0][j];
            float x1 = Xs[r0 + 1][j];
            float x2 = Xs[r0 + 2][j];
            float x3 = Xs[r0 + 3][j];
            acc[0][0] += x0 * w.x; acc[0][1] += x0 * w.y; acc[0][2] += x0 * w.z; acc[0][3] += x0 * w.w;
            acc[1][0] += x1 * w.x; acc[1][1] += x1 * w.y; acc[1][2] += x1 * w.z; acc[1][3] += x1 * w.w;
            acc[2][0] += x2 * w.x; acc[2][1] += x2 * w.y; acc[2][2] += x2 * w.z; acc[2][3] += x2 * w.w;
            acc[3][0] += x3 * w.x; acc[3][1] += x3 * w.y; acc[3][2] += x3 * w.z; acc[3][3] += x3 * w.w;
        }

        float4* H4 = (float4*)g_h;
#pragma unroll
        for (int r = 0; r < 4; r++) {
            int row = row0 + r0 + r;
            if (row < n_nodes)
                H4[row * 16 + cg] = make_float4(acc[r][0], acc[r][1], acc[r][2], acc[r][3]);
        }
    } else {
        // ---------------- PLACE role ----------------
        int b = blockIdx.x - gemm_blocks;
        int base = (b * 256 + tid) * 4;
        if (base + 4 <= n_edges) {
            int4   s4 = *(const int4*)(src + base);
            int4   d4 = *(const int4*)(dst + base);
            float4 v4 = *(const float4*)(val + base);
#pragma unroll
            for (int k = 0; k < 4; k++) {
                int d = (k == 0) ? d4.x : (k == 1) ? d4.y : (k == 2) ? d4.z : d4.w;
                int s = (k == 0) ? s4.x : (k == 1) ? s4.y : (k == 2) ? s4.z : s4.w;
                float v = (k == 0) ? v4.x : (k == 1) ? v4.y : (k == 2) ? v4.z : v4.w;
                int slot = atomicAdd(&g_count[d], 1);
                if (slot < CAP) {
                    unsigned long long rec =
                        ((unsigned long long)(unsigned)__float_as_int(v) << 32) |
                        (unsigned long long)(unsigned)s;
                    g_edge[(size_t)d * CAP + slot] = rec;
                }
            }
        } else {
            for (int e = base; e < n_edges; e++) {
                int d = dst[e];
                int slot = atomicAdd(&g_count[d], 1);
                if (slot < CAP) {
                    unsigned long long rec =
                        ((unsigned long long)(unsigned)__float_as_int(val[e]) << 32) |
                        (unsigned long long)(unsigned)src[e];
                    g_edge[(size_t)d * CAP + slot] = rec;
                }
            }
        }
    }
}

// ---------------------------------------------------------------------
// K2: warp-per-node gather-aggregate + ReLU (R8 structure, widened).
// Lane handles 2 cols (float2). Main loop: 8 edges in flight per warp,
// all record loads hoisted, exact loop bounds (no predicated gathers).
// Also resets g_count[node] for the next launch.
// ---------------------------------------------------------------------
__global__ void agg_kernel(float2* __restrict__ out2, int n_nodes) {
    int node = (blockIdx.x * blockDim.x + threadIdx.x) >> 5;
    int lane = threadIdx.x & 31;
    if (node >= n_nodes) return;

    const float2* __restrict__ h2 = (const float2*)g_h;
    const unsigned long long* __restrict__ ep = g_edge + (size_t)node * CAP;

    int cnt = g_count[node];
    if (cnt > CAP) cnt = CAP;
    if (lane == 0) g_count[node] = 0;   // reset for next launch (replaces zero_kernel)

    float2 a0 = {0.f,0.f}, a1 = {0.f,0.f}, a2 = {0.f,0.f}, a3 = {0.f,0.f};

    int i = 0;
    for (; i + 8 <= cnt; i += 8) {
        unsigned long long r0 = __ldg(ep + i + 0);
        unsigned long long r1 = __ldg(ep + i + 1);
        unsigned long long r2 = __ldg(ep + i + 2);
        unsigned long long r3 = __ldg(ep + i + 3);
        unsigned long long r4 = __ldg(ep + i + 4);
        unsigned long long r5 = __ldg(ep + i + 5);
        unsigned long long r6 = __ldg(ep + i + 6);
        unsigned long long r7 = __ldg(ep + i + 7);
        int s0 = (int)(unsigned)r0, s1 = (int)(unsigned)r1;
        int s2 = (int)(unsigned)r2, s3 = (int)(unsigned)r3;
        int s4 = (int)(unsigned)r4, s5 = (int)(unsigned)r5;
        int s6 = (int)(unsigned)r6, s7 = (int)(unsigned)r7;
        float v0 = __int_as_float((int)(r0 >> 32));
        float v1 = __int_as_float((int)(r1 >> 32));
        float v2 = __int_as_float((int)(r2 >> 32));
        float v3 = __int_as_float((int)(r3 >> 32));
        float v4 = __int_as_float((int)(r4 >> 32));
        float v5 = __int_as_float((int)(r5 >> 32));
        float v6 = __int_as_float((int)(r6 >> 32));
        float v7 = __int_as_float((int)(r7 >> 32));
        float2 x0 = h2[s0 * 32 + lane];
        float2 x1 = h2[s1 * 32 + lane];
        float2 x2 = h2[s2 * 32 + lane];
        float2 x3 = h2[s3 * 32 + lane];
        float2 x4 = h2[s4 * 32 + lane];
        float2 x5 = h2[s5 * 32 + lane];
        float2 x6 = h2[s6 * 32 + lane];
        float2 x7 = h2[s7 * 32 + lane];
        a0.x += v0 * x0.x; a0.y += v0 * x0.y;
        a1.x += v1 * x1.x; a1.y += v1 * x1.y;
        a2.x += v2 * x2.x; a2.y += v2 * x2.y;
        a3.x += v3 * x3.x; a3.y += v3 * x3.y;
        a0.x += v4 * x4.x; a0.y += v4 * x4.y;
        a1.x += v5 * x5.x; a1.y += v5 * x5.y;
        a2.x += v6 * x6.x; a2.y += v6 * x6.y;
        a3.x += v7 * x7.x; a3.y += v7 * x7.y;
    }
    for (; i + 4 <= cnt; i += 4) {
        unsigned long long r0 = __ldg(ep + i + 0);
        unsigned long long r1 = __ldg(ep + i + 1);
        unsigned long long r2 = __ldg(ep + i + 2);
        unsigned long long r3 = __ldg(ep + i + 3);
        int s0 = (int)(unsigned)r0, s1 = (int)(unsigned)r1;
        int s2 = (int)(unsigned)r2, s3 = (int)(unsigned)r3;
        float v0 = __int_as_float((int)(r0 >> 32));
        float v1 = __int_as_float((int)(r1 >> 32));
        float v2 = __int_as_float((int)(r2 >> 32));
        float v3 = __int_as_float((int)(r3 >> 32));
        float2 x0 = h2[s0 * 32 + lane];
        float2 x1 = h2[s1 * 32 + lane];
        float2 x2 = h2[s2 * 32 + lane];
        float2 x3 = h2[s3 * 32 + lane];
        a0.x += v0 * x0.x; a0.y += v0 * x0.y;
        a1.x += v1 * x1.x; a1.y += v1 * x1.y;
        a2.x += v2 * x2.x; a2.y += v2 * x2.y;
        a3.x += v3 * x3.x; a3.y += v3 * x3.y;
    }
    for (; i < cnt; i++) {
        unsigned long long r = __ldg(ep + i);
        int   s = (int)(unsigned)r;
        float v = __int_as_float((int)(r >> 32));
        float2 x = h2[s * 32 + lane];
        a0.x += v * x.x; a0.y += v * x.y;
    }

    float2 o;
    o.x = fmaxf((a0.x + a1.x) + (a2.x + a3.x), 0.f);
    o.y = fmaxf((a0.y + a1.y) + (a2.y + a3.y), 0.f);
    out2[node * 32 + lane] = o;
}

// ---------------------------------------------------------------------
extern "C" void kernel_launch(void* const* d_in, const int* in_sizes, int n_in,
                              void* d_out, int out_size) {
    const float* X  = (const float*)d_in[0];   // [N, 64]
    const float* W  = (const float*)d_in[1];   // [64, 64]
    const float* ev = (const float*)d_in[2];   // [E]
    const int*   es = (const int*)d_in[3];     // [E]
    const int*   ed = (const int*)d_in[4];     // [E]

    int n_nodes = in_sizes[0] / 64;
    int n_edges = in_sizes[2];

    int gemm_blocks  = (n_nodes + 63) / 64;
    int place_blocks = (n_edges + 1023) / 1024;   // 256 thr x 4 edges

    fused_gemm_place_kernel<<<gemm_blocks + place_blocks, 256>>>(
        (const float4*)X, (const float4*)W, es, ed, ev,
        n_nodes, n_edges, gemm_blocks);

    int blocks = (n_nodes + 7) / 8;               // 8 warps (nodes) per block
    agg_kernel<<<blocks, 256>>>((float2*)d_out, n_nodes);
}

// round 14
// speedup vs baseline: 2.3261x; 2.3261x over previous
#include <cuda_runtime.h>

// SparseGCNLayer: out = relu( segment_sum( (X@W)[src] * val -> dst ) )
// N = 100000, E = 1600000, 64 -> 64 features, fp32.
//
// R13: exact R8 pipeline (known 100.6us: zero -> gemm -> place -> agg,
// agg 4-wide, no reset-in-agg, place 1 edge/thread) with ONE change:
// gemm and place merged into a single fat kernel so their disjoint
// resource profiles (FMA+smem vs L2-atomics+scattered stores) overlap.

#define NN  100000
#define NE  1600000
#define CAP 80            // max degree capacity; Poisson(16) tail << 1e-30

// -------- scratch (__device__ globals; zero-initialized .bss) ---------
__device__ __align__(16) static float              g_h[NN * 64];             // X @ W
__device__ __align__(16) static int                g_count[NN];
__device__ __align__(16) static unsigned long long g_edge[(size_t)NN * CAP]; // hi: val bits, lo: src

// ---------------------------------------------------------------------
// K1: zero per-dst counters (R8 verbatim)
// ---------------------------------------------------------------------
__global__ void zero_kernel(int n_nodes) {
    int i = blockIdx.x * blockDim.x + threadIdx.x;
    if (i < n_nodes) g_count[i] = 0;
}

// ---------------------------------------------------------------------
// K2 (fat): blocks [0, gemm_blocks) do h = X @ W (64x64 tile, 4x4/thread);
//           blocks [gemm_blocks, ...) place edges, 1 edge per thread
//           (identical access pattern to R8's place_kernel).
// ---------------------------------------------------------------------
__global__ void fused_gemm_place_kernel(const float4* __restrict__ X4,
                                        const float4* __restrict__ W4,
                                        const int*    __restrict__ src,
                                        const int*    __restrict__ dst,
                                        const float*  __restrict__ val,
                                        int n_nodes, int n_edges,
                                        int gemm_blocks) {
    __shared__ float Ws[64][64];
    __shared__ float Xs[64][68];      // padded to dodge bank conflicts

    const int tid = threadIdx.x;      // 256 threads

    if (blockIdx.x < gemm_blocks) {
        // ---------------- GEMM role (R8 gemm verbatim) ----------------
        const int row0 = blockIdx.x * 64;

        for (int k = tid; k < 1024; k += 256) {
            float4 w = W4[k];
            int j = k >> 4, c = (k & 15) * 4;
            Ws[j][c + 0] = w.x; Ws[j][c + 1] = w.y;
            Ws[j][c + 2] = w.z; Ws[j][c + 3] = w.w;
        }
        for (int k = tid; k < 1024; k += 256) {
            int r = k >> 4, cq = (k & 15);
            int row = row0 + r;
            float4 x = (row < n_nodes) ? X4[row * 16 + cq]
                                       : make_float4(0.f, 0.f, 0.f, 0.f);
            int c = cq * 4;
            Xs[r][c + 0] = x.x; Xs[r][c + 1] = x.y;
            Xs[r][c + 2] = x.z; Xs[r][c + 3] = x.w;
        }
        __syncthreads();

        const int cg = tid & 15;
        const int rg = tid >> 4;
        const int c0 = cg * 4;
        const int r0 = rg * 4;

        float acc[4][4] = {};
#pragma unroll
        for (int j = 0; j < 64; j++) {
            float4 w = *(const float4*)&Ws[j][c0];
            float x0 = Xs[r0 + 0][j];
            float x1 = Xs[r0 + 1][j];
            float x2 = Xs[r0 + 2][j];
            float x3 = Xs[r0 + 3][j];
            acc[0][0] += x0 * w.x; acc[0][1] += x0 * w.y; acc[0][2] += x0 * w.z; acc[0][3] += x0 * w.w;
            acc[1][0] += x1 * w.x; acc[1][1] += x1 * w.y; acc[1][2] += x1 * w.z; acc[1][3] += x1 * w.w;
            acc[2][0] += x2 * w.x; acc[2][1] += x2 * w.y; acc[2][2] += x2 * w.z; acc[2][3] += x2 * w.w;
            acc[3][0] += x3 * w.x; acc[3][1] += x3 * w.y; acc[3][2] += x3 * w.z; acc[3][3] += x3 * w.w;
        }

        float4* H4 = (float4*)g_h;
#pragma unroll
        for (int r = 0; r < 4; r++) {
            int row = row0 + r0 + r;
            if (row < n_nodes)
                H4[row * 16 + cg] = make_float4(acc[r][0], acc[r][1], acc[r][2], acc[r][3]);
        }
    } else {
        // ---------------- PLACE role (R8 place verbatim: 1 edge/thread) ----
        int e = (blockIdx.x - gemm_blocks) * 256 + tid;
        if (e < n_edges) {
            int d = dst[e];
            int slot = atomicAdd(&g_count[d], 1);
            if (slot < CAP) {
                unsigned long long rec =
                    ((unsigned long long)(unsigned)__float_as_int(val[e]) << 32) |
                    (unsigned long long)(unsigned)src[e];
                g_edge[(size_t)d * CAP + slot] = rec;
            }
        }
    }
}

// ---------------------------------------------------------------------
// K3: warp-per-node gather-aggregate + ReLU — R8 VERBATIM (4-wide,
// no counter reset). Lane handles 2 cols (float2).
// ---------------------------------------------------------------------
__global__ void agg_kernel(float2* __restrict__ out2, int n_nodes) {
    int node = (blockIdx.x * blockDim.x + threadIdx.x) >> 5;
    int lane = threadIdx.x & 31;
    if (node >= n_nodes) return;

    const float2* __restrict__ h2 = (const float2*)g_h;
    const unsigned long long* __restrict__ ep = g_edge + (size_t)node * CAP;
    int cnt = g_count[node];
    if (cnt > CAP) cnt = CAP;

    float2 a0 = {0.f, 0.f}, a1 = {0.f, 0.f}, a2 = {0.f, 0.f}, a3 = {0.f, 0.f};
    int i = 0;
    for (; i + 4 <= cnt; i += 4) {
        unsigned long long r0 = __ldg(ep + i + 0);
        unsigned long long r1 = __ldg(ep + i + 1);
        unsigned long long r2 = __ldg(ep + i + 2);
        unsigned long long r3 = __ldg(ep + i + 3);
        int   s0 = (int)(unsigned)r0,        s1 = (int)(unsigned)r1;
        int   s2 = (int)(unsigned)r2,        s3 = (int)(unsigned)r3;
        float v0 = __int_as_float((int)(r0 >> 32));
        float v1 = __int_as_float((int)(r1 >> 32));
        float v2 = __int_as_float((int)(r2 >> 32));
        float v3 = __int_as_float((int)(r3 >> 32));
        float2 x0 = h2[s0 * 32 + lane];
        float2 x1 = h2[s1 * 32 + lane];
        float2 x2 = h2[s2 * 32 + lane];
        float2 x3 = h2[s3 * 32 + lane];
        a0.x += v0 * x0.x; a0.y += v0 * x0.y;
        a1.x += v1 * x1.x; a1.y += v1 * x1.y;
        a2.x += v2 * x2.x; a2.y += v2 * x2.y;
        a3.x += v3 * x3.x; a3.y += v3 * x3.y;
    }
    for (; i < cnt; i++) {
        unsigned long long r = __ldg(ep + i);
        int   s = (int)(unsigned)r;
        float v = __int_as_float((int)(r >> 32));
        float2 x = h2[s * 32 + lane];
        a0.x += v * x.x; a0.y += v * x.y;
    }
    float2 o;
    o.x = fmaxf(a0.x + a1.x + a2.x + a3.x, 0.f);
    o.y = fmaxf(a0.y + a1.y + a2.y + a3.y, 0.f);
    out2[node * 32 + lane] = o;
}

// ---------------------------------------------------------------------
extern "C" void kernel_launch(void* const* d_in, const int* in_sizes, int n_in,
                              void* d_out, int out_size) {
    const float* X  = (const float*)d_in[0];   // [N, 64]
    const float* W  = (const float*)d_in[1];   // [64, 64]
    const float* ev = (const float*)d_in[2];   // [E]
    const int*   es = (const int*)d_in[3];     // [E]
    const int*   ed = (const int*)d_in[4];     // [E]

    int n_nodes = in_sizes[0] / 64;
    int n_edges = in_sizes[2];

    int gemm_blocks  = (n_nodes + 63) / 64;
    int place_blocks = (n_edges + 255) / 256;  // 1 edge per thread (R8 pattern)

    zero_kernel<<<(n_nodes + 255) / 256, 256>>>(n_nodes);
    fused_gemm_place_kernel<<<gemm_blocks + place_blocks, 256>>>(
        (const float4*)X, (const float4*)W, es, ed, ev,
        n_nodes, n_edges, gemm_blocks);

    int blocks = (n_nodes + 7) / 8;            // 8 warps (nodes) per block
    agg_kernel<<<blocks, 256>>>((float2*)d_out, n_nodes);
}